// round 12
// baseline (speedup 1.0000x reference)
#include <cuda_runtime.h>
#include <cuda_bf16.h>

#define HD    1024
#define SLEN  256
#define TLEN  256
#define VOUT  32000
#define G4    4096
#define NCTA_REC 128
#define NCTA_TOTAL 148
#define NSPARE (NCTA_TOTAL - NCTA_REC)
#define STEPS 512
#define GSL_STRIDE 33   // bank-conflict padding for gsl rows
#define LPAD 72         // smem row padding (bf16) for conflict-free ldmatrix
#define VTILES (VOUT / 128)      // 250 vocab tiles
#define HIDDEN_TILES (2 * VTILES) // token chunks 0,1 computed by spare CTAs

// ---------------- device scratch ----------------
__device__ __nv_bfloat16 g_linw_bf[(size_t)VOUT * HD];   // 65.5 MB
__device__ __nv_bfloat16 g_wih_bf[2ul * G4 * HD];        // 16.8 MB
__device__ __nv_bfloat16 g_xbf[(size_t)STEPS * HD];      // 1 MB
__device__ float         g_G[2ul * G4 * SLEN];           // 8 MB, [net][gate_row][token]
__device__ __nv_bfloat16 g_Hbf[(size_t)TLEN * HD];       // 0.5 MB
__device__ float         g_hbuf[2][HD];
__device__ unsigned      g_cnt[STEPS + 1];
__device__ unsigned      g_cnt2;                          // linW conversion done count

// ---------------- helpers ----------------
__device__ __forceinline__ void ffma2(unsigned long long &d,
                                      unsigned long long a, unsigned long long b) {
    asm("fma.rn.f32x2 %0, %1, %2, %0;" : "+l"(d) : "l"(a), "l"(b));
}
__device__ __forceinline__ void unpack2(unsigned long long v, float &lo, float &hi) {
    unsigned l, h;
    asm("mov.b64 {%0, %1}, %2;" : "=r"(l), "=r"(h) : "l"(v));
    lo = __uint_as_float(l); hi = __uint_as_float(h);
}
__device__ __forceinline__ unsigned ld_acq(const unsigned* p) {
    unsigned v;
    asm volatile("ld.acquire.gpu.global.u32 %0, [%1];" : "=r"(v) : "l"(p) : "memory");
    return v;
}
__device__ __forceinline__ void red_rel(unsigned* p) {
    asm volatile("red.release.gpu.global.add.u32 [%0], 1;" :: "l"(p) : "memory");
}
__device__ __forceinline__ float tanh_hw(float x) {
    float y;
    asm("tanh.approx.f32 %0, %1;" : "=f"(y) : "f"(x));
    return y;
}
__device__ __forceinline__ float sig_hw(float x) {
    return fmaf(tanh_hw(0.5f * x), 0.5f, 0.5f);
}
__device__ __forceinline__ void mma_bf16(float c[4],
                                         unsigned a0, unsigned a1, unsigned a2, unsigned a3,
                                         unsigned b0, unsigned b1) {
    asm volatile("mma.sync.aligned.m16n8k16.row.col.f32.bf16.bf16.f32 "
                 "{%0,%1,%2,%3}, {%4,%5,%6,%7}, {%8,%9}, {%0,%1,%2,%3};"
                 : "+f"(c[0]), "+f"(c[1]), "+f"(c[2]), "+f"(c[3])
                 : "r"(a0), "r"(a1), "r"(a2), "r"(a3), "r"(b0), "r"(b1));
}
__device__ __forceinline__ unsigned smem_u32(const void* p) {
    return (unsigned)__cvta_generic_to_shared(p);
}
__device__ __forceinline__ void ldsm_x4(unsigned &r0, unsigned &r1,
                                        unsigned &r2, unsigned &r3, unsigned addr) {
    asm volatile("ldmatrix.sync.aligned.m8n8.x4.shared.b16 {%0,%1,%2,%3}, [%4];"
                 : "=r"(r0), "=r"(r1), "=r"(r2), "=r"(r3) : "r"(addr));
}

// ---------------- shared logits tile: 128 vocab x 64 tokens x K=1024 ----------------
__device__ void logits_tile(size_t bm, int bn, const float* __restrict__ lin_b,
                            float* __restrict__ out,
                            __nv_bfloat16* sA, __nv_bfloat16* sB, int tid) {
    const int w = tid >> 5, lane = tid & 31;
    const int group = lane >> 2, tig = lane & 3;

    float acc[8][4];
    #pragma unroll
    for (int nf = 0; nf < 8; nf++)
        #pragma unroll
        for (int q = 0; q < 4; q++) acc[nf][q] = 0.f;

    const int mi = lane >> 3, r8 = lane & 7;
    const int a_row = 16 * w + r8 + ((mi & 1) ? 8 : 0);
    const int a_col = (mi & 2) ? 8 : 0;

    for (int k0 = 0; k0 < HD; k0 += 64) {
        #pragma unroll
        for (int i = tid; i < 128 * 8; i += 256) {
            const int row = i >> 3, c = i & 7;
            *(uint4*)&sA[row * LPAD + c * 8] =
                *(const uint4*)&g_linw_bf[(bm + row) * HD + k0 + c * 8];
        }
        #pragma unroll
        for (int i = tid; i < 64 * 8; i += 256) {
            const int row = i >> 3, c = i & 7;
            *(uint4*)&sB[row * LPAD + c * 8] =
                *(const uint4*)&g_Hbf[(size_t)(bn + row) * HD + k0 + c * 8];
        }
        __syncthreads();

        #pragma unroll
        for (int kk = 0; kk < 64; kk += 16) {
            unsigned a[4];
            ldsm_x4(a[0], a[1], a[2], a[3],
                    smem_u32(&sA[a_row * LPAD + kk + a_col]));
            unsigned b[8][2];
            #pragma unroll
            for (int p = 0; p < 4; p++) {
                const int b_row = (2 * p + (mi >> 1)) * 8 + r8;
                const int b_col = kk + ((mi & 1) ? 8 : 0);
                ldsm_x4(b[2 * p][0], b[2 * p][1], b[2 * p + 1][0], b[2 * p + 1][1],
                        smem_u32(&sB[b_row * LPAD + b_col]));
            }
            #pragma unroll
            for (int nf = 0; nf < 8; nf++)
                mma_bf16(acc[nf], a[0], a[1], a[2], a[3], b[nf][0], b[nf][1]);
        }
        __syncthreads();
    }

    const size_t m0 = bm + 16 * w + group;
    const float bias0 = lin_b[m0];
    const float bias8 = lin_b[m0 + 8];
    #pragma unroll
    for (int nf = 0; nf < 8; nf++) {
        const int n = bn + nf * 8 + 2 * tig;
        out[(size_t)n * VOUT + m0]           = acc[nf][0] + bias0;
        out[(size_t)(n + 1) * VOUT + m0]     = acc[nf][1] + bias0;
        out[(size_t)n * VOUT + m0 + 8]       = acc[nf][2] + bias8;
        out[(size_t)(n + 1) * VOUT + m0 + 8] = acc[nf][3] + bias8;
    }
}

// ---------------- 1) prep: embedding gather + Wih conversion + counter reset ----------------
__global__ void prep_kernel(const int* __restrict__ src, const int* __restrict__ trg,
                            const int* __restrict__ start,
                            const float* __restrict__ enc_emb,
                            const float* __restrict__ dec_emb,
                            const float* __restrict__ encWih,
                            const float* __restrict__ decWih) {
    const int b = blockIdx.x;           // 0..639
    const int tid = threadIdx.x;        // 256
    if (b < STEPS) {
        const int t = b;
        if (t == 0) {
            for (int i = tid; i < STEPS + 1; i += 256) g_cnt[i] = 0;
            if (tid == 0) g_cnt2 = 0;
        }
        const float* emb; int tok;
        if (t < SLEN) { tok = src[t]; emb = enc_emb; }
        else {
            int tt = t - SLEN;
            tok = (tt == 0) ? start[0] : trg[tt - 1];
            emb = dec_emb;
        }
        const float4 v = ((const float4*)(emb + (size_t)tok * HD))[tid];
        __nv_bfloat162* d = (__nv_bfloat162*)(g_xbf + (size_t)t * HD);
        d[2 * tid]     = __floats2bfloat162_rn(v.x, v.y);
        d[2 * tid + 1] = __floats2bfloat162_rn(v.z, v.w);
    } else {
        const size_t NW4 = (size_t)G4 * HD / 4;
        size_t i = (size_t)(b - STEPS) * 256 + tid;
        const size_t stride = 128ul * 256;
        const float4* se = (const float4*)encWih;
        const float4* sd = (const float4*)decWih;
        __nv_bfloat162* de = (__nv_bfloat162*)g_wih_bf;
        __nv_bfloat162* dd = (__nv_bfloat162*)(g_wih_bf + (size_t)G4 * HD);
        for (size_t j = i; j < NW4; j += stride) {
            const float4 ve = se[j];
            de[2 * j]     = __floats2bfloat162_rn(ve.x, ve.y);
            de[2 * j + 1] = __floats2bfloat162_rn(ve.z, ve.w);
            const float4 vd = sd[j];
            dd[2 * j]     = __floats2bfloat162_rn(vd.x, vd.y);
            dd[2 * j + 1] = __floats2bfloat162_rn(vd.z, vd.w);
        }
    }
}

// ---------------- 3) G^T = Wih @ X^T + (bih+bhh), tensor cores ----------------
__global__ void __launch_bounds__(128) wx_mma(const float* __restrict__ eb_ih,
                                              const float* __restrict__ eb_hh,
                                              const float* __restrict__ db_ih,
                                              const float* __restrict__ db_hh) {
    const int net = blockIdx.z;
    const __nv_bfloat16* A = g_wih_bf + (size_t)net * G4 * HD;
    const __nv_bfloat16* B = g_xbf + (size_t)net * SLEN * HD;
    const float* bih = net ? db_ih : eb_ih;
    const float* bhh = net ? db_hh : eb_hh;
    float* Gout = g_G + (size_t)net * G4 * SLEN;

    const int tid = threadIdx.x;
    const int w = tid >> 5, lane = tid & 31;
    const int group = lane >> 2, tig = lane & 3;
    const int bm = blockIdx.x * 128 + w * 32;
    const int bn = blockIdx.y * 64;

    float acc[2][8][4];
    #pragma unroll
    for (int mf = 0; mf < 2; mf++)
        #pragma unroll
        for (int nf = 0; nf < 8; nf++)
            #pragma unroll
            for (int q = 0; q < 4; q++) acc[mf][nf][q] = 0.f;

    for (int k0 = 0; k0 < HD; k0 += 16) {
        unsigned a[2][4], b[8][2];
        #pragma unroll
        for (int mf = 0; mf < 2; mf++) {
            const __nv_bfloat16* ab = A + (size_t)(bm + mf * 16 + group) * HD + k0 + 2 * tig;
            a[mf][0] = *(const unsigned*)(ab);
            a[mf][1] = *(const unsigned*)(ab + 8 * HD);
            a[mf][2] = *(const unsigned*)(ab + 8);
            a[mf][3] = *(const unsigned*)(ab + 8 * HD + 8);
        }
        #pragma unroll
        for (int nf = 0; nf < 8; nf++) {
            const __nv_bfloat16* bb = B + (size_t)(bn + nf * 8 + group) * HD + k0 + 2 * tig;
            b[nf][0] = *(const unsigned*)(bb);
            b[nf][1] = *(const unsigned*)(bb + 8);
        }
        #pragma unroll
        for (int mf = 0; mf < 2; mf++)
            #pragma unroll
            for (int nf = 0; nf < 8; nf++)
                mma_bf16(acc[mf][nf], a[mf][0], a[mf][1], a[mf][2], a[mf][3],
                         b[nf][0], b[nf][1]);
    }
    #pragma unroll
    for (int mf = 0; mf < 2; mf++) {
        const int m0 = bm + mf * 16 + group;
        const float bias0 = bih[m0] + bhh[m0];
        const float bias8 = bih[m0 + 8] + bhh[m0 + 8];
        #pragma unroll
        for (int nf = 0; nf < 8; nf++) {
            const int n = bn + nf * 8 + 2 * tig;
            float2 s0; s0.x = acc[mf][nf][0] + bias0; s0.y = acc[mf][nf][1] + bias0;
            float2 s8; s8.x = acc[mf][nf][2] + bias8; s8.y = acc[mf][nf][3] + bias8;
            *(float2*)&Gout[(size_t)m0 * SLEN + n]       = s0;
            *(float2*)&Gout[(size_t)(m0 + 8) * SLEN + n] = s8;
        }
    }
}

// ---------------- 4) persistent LSTM recurrence + hidden linW convert + hidden logits ----------------
__device__ __forceinline__ void load_w(ulonglong2 (&wv)[4][8], const float* __restrict__ W,
                                       int w, int lane, int base) {
    #pragma unroll
    for (int j = 0; j < 4; j++) {
        const int r = w * 4 + j, q = r >> 3, u = r & 7;
        const float* row = W + (size_t)(q * HD + base + u) * HD + lane * 4;
        #pragma unroll
        for (int c = 0; c < 8; c++)
            wv[j][c] = *(const ulonglong2*)(row + c * 128);
    }
}

__global__ void __launch_bounds__(256, 1) rec_kernel(const float* __restrict__ encWhh,
                                                     const float* __restrict__ decWhh,
                                                     const float* __restrict__ linW,
                                                     const float* __restrict__ lin_b,
                                                     float* __restrict__ out) {
    extern __shared__ float sm[];
    const int tid = threadIdx.x, cta = blockIdx.x;

    if (cta >= NCTA_REC) {
        // ---- phase 1: linW f32 -> bf16 on the 20 spare SMs ----
        {
            const size_t NL4 = (size_t)VOUT * HD / 4;
            size_t i = (size_t)(cta - NCTA_REC) * 256 + tid;
            const size_t stride = (size_t)NSPARE * 256;
            const float4* src = (const float4*)linW;
            __nv_bfloat162* dst = (__nv_bfloat162*)g_linw_bf;
            for (size_t j = i; j < NL4; j += stride) {
                const float4 v = src[j];
                dst[2 * j]     = __floats2bfloat162_rn(v.x, v.y);
                dst[2 * j + 1] = __floats2bfloat162_rn(v.z, v.w);
            }
        }
        __syncthreads();
        if (tid == 0) red_rel(&g_cnt2);
        // wait for ALL spare CTAs' conversion slices (logits tiles read all of linW)
        if (tid == 0) { while (ld_acq(&g_cnt2) < NSPARE) {} }
        __syncthreads();

        // ---- phase 2: logits tiles for token chunks 0,1 as h rows become ready ----
        __nv_bfloat16* sA = (__nv_bfloat16*)sm;
        __nv_bfloat16* sB = sA + 128 * LPAD;
        const int s = cta - NCTA_REC;
        for (int j = s; j < HIDDEN_TILES; j += NSPARE) {
            const int chunk = j / VTILES;            // 0 or 1 -> tokens [64c, 64c+64)
            const size_t bm = (size_t)(j % VTILES) * 128;
            const int bn = chunk * 64;
            // tokens < bn+64 are published once all CTAs passed step SLEN+bn+64
            if (tid == 0) { while (ld_acq(&g_cnt[SLEN + bn + 64]) < NCTA_REC) {} }
            __syncthreads();
            logits_tile(bm, bn, lin_b, out, sA, sB, tid);
        }
        return;
    }

    float* gsl    = sm;                        // [512][GSL_STRIDE] Wx+bias gates
    float* h_s    = gsl + STEPS * GSL_STRIDE;  // [1024]
    float* gate_s = h_s + HD;                  // [32]

    const int w = tid >> 5, lane = tid & 31;
    const int base = cta * 8;

    for (int i = tid; i < STEPS * 32; i += 256) {
        const int r = i >> 9, s = i & 511;
        const int net = s >> 8, sl = s & 255;
        const int q = r >> 3, u = r & 7;
        gsl[s * GSL_STRIDE + r] =
            g_G[(size_t)net * G4 * SLEN + (size_t)(q * HD + base + u) * SLEN + sl];
    }

    ulonglong2 wv[4][8];
    load_w(wv, encWhh, w, lane, base);

    float cstate = 0.f;
    if (tid < 8) {
        g_hbuf[0][base + tid] = 0.f;
        __syncwarp(0xff);
        if (tid == 0) red_rel(&g_cnt[0]);
    }
    __syncthreads();

    for (int t = 0; t < STEPS; t++) {
        if (t == SLEN) load_w(wv, decWhh, w, lane, base);

        if (tid == 0) { while (ld_acq(&g_cnt[t]) < NCTA_REC) {} }
        __syncthreads();
        ((float4*)h_s)[tid] = ((const float4*)g_hbuf[t & 1])[tid];
        __syncthreads();

        unsigned long long acc2[4] = {0ull, 0ull, 0ull, 0ull};
        #pragma unroll
        for (int c = 0; c < 8; c++) {
            const ulonglong2 hv = *(const ulonglong2*)(h_s + lane * 4 + c * 128);
            #pragma unroll
            for (int j = 0; j < 4; j++) {
                ffma2(acc2[j], wv[j][c].x, hv.x);
                ffma2(acc2[j], wv[j][c].y, hv.y);
            }
        }
        float accf[4];
        #pragma unroll
        for (int j = 0; j < 4; j++) {
            float lo, hi; unpack2(acc2[j], lo, hi);
            accf[j] = lo + hi;
        }
        #pragma unroll
        for (int off = 16; off; off >>= 1) {
            #pragma unroll
            for (int j = 0; j < 4; j++)
                accf[j] += __shfl_xor_sync(0xffffffffu, accf[j], off);
        }
        if (lane < 4) gate_s[w * 4 + lane] = accf[lane];
        __syncthreads();

        if (w == 0) {
            const int q = lane >> 3, u = lane & 7;
            const float val = gate_s[lane] + gsl[t * GSL_STRIDE + lane];
            const float act = (q == 2) ? tanh_hw(val) : sig_hw(val);
            const float iv = __shfl_sync(0xffffffffu, act, u);
            const float fv = __shfl_sync(0xffffffffu, act, u + 8);
            const float gv = __shfl_sync(0xffffffffu, act, u + 16);
            const float ov = __shfl_sync(0xffffffffu, act, u + 24);
            if (lane < 8) {
                cstate = fv * cstate + iv * gv;
                const float hh = ov * tanh_hw(cstate);
                g_hbuf[(t + 1) & 1][base + lane] = hh;
                if (t >= SLEN) g_Hbf[(size_t)(t - SLEN) * HD + base + lane] = __float2bfloat16(hh);
            }
            __syncwarp();
            if (lane == 0) red_rel(&g_cnt[t + 1]);
        }
    }
}

// ---------------- 5) logits for token chunks 2,3 (post-recurrence) ----------------
__global__ void __launch_bounds__(256) logits_mma(const float* __restrict__ lin_b,
                                                  float* __restrict__ out) {
    __shared__ __nv_bfloat16 sA[128 * LPAD];
    __shared__ __nv_bfloat16 sB[64 * LPAD];
    const size_t bm = (size_t)blockIdx.x * 128;
    const int bn = 128 + blockIdx.y * 64;
    logits_tile(bm, bn, lin_b, out, sA, sB, threadIdx.x);
}

// ---------------- 6) in-place row log_softmax (online, float4, 512 thr) ----------------
__global__ void __launch_bounds__(512) logsoftmax_kernel(float* __restrict__ out) {
    const int t = blockIdx.x;
    float* row = out + (size_t)t * VOUT;
    const int tid = threadIdx.x;
    __shared__ float smx[16], ssm[16];
    __shared__ float sbcast;

    float4* r4 = (float4*)row;
    float m = -3.4e38f, s = 0.f;
    for (int i = tid; i < VOUT / 4; i += 512) {
        const float4 v = r4[i];
        const float vm = fmaxf(fmaxf(v.x, v.y), fmaxf(v.z, v.w));
        const float nm = fmaxf(m, vm);
        s = s * __expf(m - nm) + __expf(v.x - nm) + __expf(v.y - nm)
                               + __expf(v.z - nm) + __expf(v.w - nm);
        m = nm;
    }
    #pragma unroll
    for (int o = 16; o; o >>= 1) {
        const float mo = __shfl_xor_sync(0xffffffffu, m, o);
        const float so = __shfl_xor_sync(0xffffffffu, s, o);
        const float nm = fmaxf(m, mo);
        s = s * __expf(m - nm) + so * __expf(mo - nm);
        m = nm;
    }
    if ((tid & 31) == 0) { smx[tid >> 5] = m; ssm[tid >> 5] = s; }
    __syncthreads();
    if (tid == 0) {
        float M = smx[0], S = ssm[0];
        for (int wq = 1; wq < 16; wq++) {
            const float nm = fmaxf(M, smx[wq]);
            S = S * __expf(M - nm) + ssm[wq] * __expf(smx[wq] - nm);
            M = nm;
        }
        sbcast = M + logf(S);
    }
    __syncthreads();
    const float lse = sbcast;
    for (int i = tid; i < VOUT / 4; i += 512) {
        float4 v = r4[i];
        v.x -= lse; v.y -= lse; v.z -= lse; v.w -= lse;
        r4[i] = v;
    }
}

// ---------------- launch ----------------
extern "C" void kernel_launch(void* const* d_in, const int* in_sizes, int n_in,
                              void* d_out, int out_size) {
    const int*   src     = (const int*)d_in[0];
    const int*   trg     = (const int*)d_in[1];
    const int*   start   = (const int*)d_in[2];
    const float* enc_emb = (const float*)d_in[3];
    const float* enc_Wih = (const float*)d_in[4];
    const float* enc_Whh = (const float*)d_in[5];
    const float* enc_bih = (const float*)d_in[6];
    const float* enc_bhh = (const float*)d_in[7];
    const float* dec_emb = (const float*)d_in[8];
    const float* dec_Wih = (const float*)d_in[9];
    const float* dec_Whh = (const float*)d_in[10];
    const float* dec_bih = (const float*)d_in[11];
    const float* dec_bhh = (const float*)d_in[12];
    const float* lin_W   = (const float*)d_in[13];
    const float* lin_b   = (const float*)d_in[14];
    float* out = (float*)d_out;

    prep_kernel<<<STEPS + 128, 256>>>(src, trg, start, enc_emb, dec_emb,
                                      enc_Wih, dec_Wih);

    dim3 gwx(G4 / 128, SLEN / 64, 2);
    wx_mma<<<gwx, 128>>>(enc_bih, enc_bhh, dec_bih, dec_bhh);

    const int REC_SMEM = (STEPS * GSL_STRIDE + HD + 32) * 4;   // ~71.8 KB (>= 27.6 KB tile smem)
    cudaFuncSetAttribute(rec_kernel, cudaFuncAttributeMaxDynamicSharedMemorySize, REC_SMEM);
    rec_kernel<<<NCTA_TOTAL, 256, REC_SMEM>>>(enc_Whh, dec_Whh, lin_W, lin_b, out);

    dim3 gl(VTILES, 2);   // token chunks 2,3
    logits_mma<<<gl, 256>>>(lin_b, out);

    logsoftmax_kernel<<<TLEN, 512>>>(out);
}

// round 13
// speedup vs baseline: 1.1428x; 1.1428x over previous
#include <cuda_runtime.h>
#include <cuda_bf16.h>

#define HD    1024
#define SLEN  256
#define TLEN  256
#define VOUT  32000
#define G4    4096
#define NCTA_REC 128
#define NCTA_TOTAL 148
#define NSPARE (NCTA_TOTAL - NCTA_REC)
#define STEPS 512
#define GSL_STRIDE 33   // bank-conflict padding for gsl rows
#define LPAD 72         // smem row padding (bf16) for conflict-free ldmatrix
#define VTILES (VOUT / 128)
#define STAGE_ELEMS ((128 + 64) * LPAD)          // one pipeline stage (A+B)
#define TILE_SMEM (2 * STAGE_ELEMS * 2)          // 55296 B

// ---------------- device scratch ----------------
__device__ __nv_bfloat16 g_linw_bf[(size_t)VOUT * HD];   // 65.5 MB
__device__ __nv_bfloat16 g_wih_bf[2ul * G4 * HD];        // 16.8 MB
__device__ __nv_bfloat16 g_xbf[(size_t)STEPS * HD];      // 1 MB
__device__ float         g_G[2ul * G4 * SLEN];           // 8 MB, [net][gate_row][token]
__device__ __nv_bfloat16 g_Hbf[(size_t)TLEN * HD];       // 0.5 MB
__device__ float         g_hbuf[2][HD];
__device__ unsigned      g_cnt[STEPS + 1];

// ---------------- helpers ----------------
__device__ __forceinline__ void ffma2(unsigned long long &d,
                                      unsigned long long a, unsigned long long b) {
    asm("fma.rn.f32x2 %0, %1, %2, %0;" : "+l"(d) : "l"(a), "l"(b));
}
__device__ __forceinline__ void unpack2(unsigned long long v, float &lo, float &hi) {
    unsigned l, h;
    asm("mov.b64 {%0, %1}, %2;" : "=r"(l), "=r"(h) : "l"(v));
    lo = __uint_as_float(l); hi = __uint_as_float(h);
}
__device__ __forceinline__ unsigned ld_acq(const unsigned* p) {
    unsigned v;
    asm volatile("ld.acquire.gpu.global.u32 %0, [%1];" : "=r"(v) : "l"(p) : "memory");
    return v;
}
__device__ __forceinline__ void red_rel(unsigned* p) {
    asm volatile("red.release.gpu.global.add.u32 [%0], 1;" :: "l"(p) : "memory");
}
__device__ __forceinline__ float tanh_hw(float x) {
    float y;
    asm("tanh.approx.f32 %0, %1;" : "=f"(y) : "f"(x));
    return y;
}
__device__ __forceinline__ float sig_hw(float x) {
    return fmaf(tanh_hw(0.5f * x), 0.5f, 0.5f);
}
__device__ __forceinline__ void mma_bf16(float c[4],
                                         unsigned a0, unsigned a1, unsigned a2, unsigned a3,
                                         unsigned b0, unsigned b1) {
    asm volatile("mma.sync.aligned.m16n8k16.row.col.f32.bf16.bf16.f32 "
                 "{%0,%1,%2,%3}, {%4,%5,%6,%7}, {%8,%9}, {%0,%1,%2,%3};"
                 : "+f"(c[0]), "+f"(c[1]), "+f"(c[2]), "+f"(c[3])
                 : "r"(a0), "r"(a1), "r"(a2), "r"(a3), "r"(b0), "r"(b1));
}
__device__ __forceinline__ unsigned smem_u32(const void* p) {
    return (unsigned)__cvta_generic_to_shared(p);
}
__device__ __forceinline__ void ldsm_x4(unsigned &r0, unsigned &r1,
                                        unsigned &r2, unsigned &r3, unsigned addr) {
    asm volatile("ldmatrix.sync.aligned.m8n8.x4.shared.b16 {%0,%1,%2,%3}, [%4];"
                 : "=r"(r0), "=r"(r1), "=r"(r2), "=r"(r3) : "r"(addr));
}
__device__ __forceinline__ void cp16(void* smem, const void* gmem) {
    asm volatile("cp.async.cg.shared.global [%0], [%1], 16;"
                 :: "r"(smem_u32(smem)), "l"(gmem));
}
#define CP_COMMIT() asm volatile("cp.async.commit_group;" ::: "memory")
#define CP_WAIT1()  asm volatile("cp.async.wait_group 1;" ::: "memory")

// ---------------- double-buffered 128x64xK tile core ----------------
// A: [M rows of HD bf16] at aRow0, B: [64 rows of HD bf16] at bRow0.
// acc[nf][q] produced per warp (warp w owns rows 16w..16w+15).
__device__ __forceinline__ void tile_mainloop(const __nv_bfloat16* __restrict__ Abase,
                                              const __nv_bfloat16* __restrict__ Bbase,
                                              __nv_bfloat16* sm2, int tid,
                                              float acc[8][4]) {
    const int w = tid >> 5, lane = tid & 31;
    const int mi = lane >> 3, r8 = lane & 7;
    const int a_row = 16 * w + r8 + ((mi & 1) ? 8 : 0);
    const int a_col = (mi & 2) ? 8 : 0;

    #pragma unroll
    for (int nf = 0; nf < 8; nf++)
        #pragma unroll
        for (int q = 0; q < 4; q++) acc[nf][q] = 0.f;

    // stage prefetch helper (cp.async, 16B granules)
    auto prefetch = [&](int k0, int st) {
        __nv_bfloat16* sA = sm2 + st * STAGE_ELEMS;
        __nv_bfloat16* sB = sA + 128 * LPAD;
        #pragma unroll
        for (int i = tid; i < 128 * 8; i += 256) {
            const int row = i >> 3, c = i & 7;
            cp16(&sA[row * LPAD + c * 8], &Abase[(size_t)row * HD + k0 + c * 8]);
        }
        #pragma unroll
        for (int i = tid; i < 64 * 8; i += 256) {
            const int row = i >> 3, c = i & 7;
            cp16(&sB[row * LPAD + c * 8], &Bbase[(size_t)row * HD + k0 + c * 8]);
        }
    };

    prefetch(0, 0);
    CP_COMMIT();

    #pragma unroll 1
    for (int it = 0; it < HD / 64; it++) {
        const int cur = it & 1;
        if (it + 1 < HD / 64) prefetch((it + 1) * 64, cur ^ 1);
        CP_COMMIT();
        CP_WAIT1();
        __syncthreads();

        __nv_bfloat16* sA = sm2 + cur * STAGE_ELEMS;
        __nv_bfloat16* sB = sA + 128 * LPAD;
        #pragma unroll
        for (int kk = 0; kk < 64; kk += 16) {
            unsigned a[4];
            ldsm_x4(a[0], a[1], a[2], a[3],
                    smem_u32(&sA[a_row * LPAD + kk + a_col]));
            unsigned b[8][2];
            #pragma unroll
            for (int p = 0; p < 4; p++) {
                const int b_row = (2 * p + (mi >> 1)) * 8 + r8;
                const int b_col = kk + ((mi & 1) ? 8 : 0);
                ldsm_x4(b[2 * p][0], b[2 * p][1], b[2 * p + 1][0], b[2 * p + 1][1],
                        smem_u32(&sB[b_row * LPAD + b_col]));
            }
            #pragma unroll
            for (int nf = 0; nf < 8; nf++)
                mma_bf16(acc[nf], a[0], a[1], a[2], a[3], b[nf][0], b[nf][1]);
        }
        __syncthreads();
    }
}

// ---------------- 1) prep: embedding gather + counter reset ----------------
__global__ void prep_kernel(const int* __restrict__ src, const int* __restrict__ trg,
                            const int* __restrict__ start,
                            const float* __restrict__ enc_emb,
                            const float* __restrict__ dec_emb,
                            const float* __restrict__ encWih,
                            const float* __restrict__ decWih) {
    const int b = blockIdx.x;           // 0..639
    const int tid = threadIdx.x;        // 256
    if (b < STEPS) {
        const int t = b;
        if (t == 0) {
            for (int i = tid; i < STEPS + 1; i += 256) g_cnt[i] = 0;
        }
        const float* emb; int tok;
        if (t < SLEN) { tok = src[t]; emb = enc_emb; }
        else {
            int tt = t - SLEN;
            tok = (tt == 0) ? start[0] : trg[tt - 1];
            emb = dec_emb;
        }
        const float4 v = ((const float4*)(emb + (size_t)tok * HD))[tid];
        __nv_bfloat162* d = (__nv_bfloat162*)(g_xbf + (size_t)t * HD);
        d[2 * tid]     = __floats2bfloat162_rn(v.x, v.y);
        d[2 * tid + 1] = __floats2bfloat162_rn(v.z, v.w);
    } else {
        const size_t NW4 = (size_t)G4 * HD / 4;
        size_t i = (size_t)(b - STEPS) * 256 + tid;
        const size_t stride = 128ul * 256;
        const float4* se = (const float4*)encWih;
        const float4* sd = (const float4*)decWih;
        __nv_bfloat162* de = (__nv_bfloat162*)g_wih_bf;
        __nv_bfloat162* dd = (__nv_bfloat162*)(g_wih_bf + (size_t)G4 * HD);
        for (size_t j = i; j < NW4; j += stride) {
            const float4 ve = se[j];
            de[2 * j]     = __floats2bfloat162_rn(ve.x, ve.y);
            de[2 * j + 1] = __floats2bfloat162_rn(ve.z, ve.w);
            const float4 vd = sd[j];
            dd[2 * j]     = __floats2bfloat162_rn(vd.x, vd.y);
            dd[2 * j + 1] = __floats2bfloat162_rn(vd.z, vd.w);
        }
    }
}

// ---------------- 3) G^T = Wih @ X^T + (bih+bhh), staged+pipelined ----------------
__global__ void __launch_bounds__(256) wx_mma(const float* __restrict__ eb_ih,
                                              const float* __restrict__ eb_hh,
                                              const float* __restrict__ db_ih,
                                              const float* __restrict__ db_hh) {
    extern __shared__ __nv_bfloat16 sm2[];
    const int net = blockIdx.z;
    const int bm = blockIdx.x * 128;
    const int bn = blockIdx.y * 64;
    const int tid = threadIdx.x;
    const int w = tid >> 5, lane = tid & 31;
    const int group = lane >> 2, tig = lane & 3;

    const __nv_bfloat16* Abase = g_wih_bf + (size_t)net * G4 * HD + (size_t)bm * HD;
    const __nv_bfloat16* Bbase = g_xbf + (size_t)net * SLEN * HD + (size_t)bn * HD;
    const float* bih = net ? db_ih : eb_ih;
    const float* bhh = net ? db_hh : eb_hh;
    float* Gout = g_G + (size_t)net * G4 * SLEN;

    float acc[8][4];
    tile_mainloop(Abase, Bbase, sm2, tid, acc);

    const int m0 = bm + 16 * w + group;
    const float bias0 = bih[m0] + bhh[m0];
    const float bias8 = bih[m0 + 8] + bhh[m0 + 8];
    #pragma unroll
    for (int nf = 0; nf < 8; nf++) {
        const int n = bn + nf * 8 + 2 * tig;
        float2 s0; s0.x = acc[nf][0] + bias0; s0.y = acc[nf][1] + bias0;
        float2 s8; s8.x = acc[nf][2] + bias8; s8.y = acc[nf][3] + bias8;
        *(float2*)&Gout[(size_t)m0 * SLEN + n]       = s0;
        *(float2*)&Gout[(size_t)(m0 + 8) * SLEN + n] = s8;
    }
}

// ---------------- 4) persistent LSTM recurrence + hidden linW conversion ----------------
__device__ __forceinline__ void load_w(ulonglong2 (&wv)[4][8], const float* __restrict__ W,
                                       int w, int lane, int base) {
    #pragma unroll
    for (int j = 0; j < 4; j++) {
        const int r = w * 4 + j, q = r >> 3, u = r & 7;
        const float* row = W + (size_t)(q * HD + base + u) * HD + lane * 4;
        #pragma unroll
        for (int c = 0; c < 8; c++)
            wv[j][c] = *(const ulonglong2*)(row + c * 128);
    }
}

__global__ void __launch_bounds__(256, 1) rec_kernel(const float* __restrict__ encWhh,
                                                     const float* __restrict__ decWhh,
                                                     const float* __restrict__ linW) {
    const int tid = threadIdx.x, cta = blockIdx.x;

    if (cta >= NCTA_REC) {
        // linW f32 -> bf16 on the 20 spare SMs (hidden under recurrence)
        const size_t NL4 = (size_t)VOUT * HD / 4;
        size_t i = (size_t)(cta - NCTA_REC) * 256 + tid;
        const size_t stride = (size_t)NSPARE * 256;
        const float4* src = (const float4*)linW;
        __nv_bfloat162* dst = (__nv_bfloat162*)g_linw_bf;
        for (size_t j = i; j < NL4; j += stride) {
            const float4 v = src[j];
            dst[2 * j]     = __floats2bfloat162_rn(v.x, v.y);
            dst[2 * j + 1] = __floats2bfloat162_rn(v.z, v.w);
        }
        return;
    }

    extern __shared__ float sm[];
    float* gsl    = sm;                        // [512][GSL_STRIDE] Wx+bias gates
    float* h_s    = gsl + STEPS * GSL_STRIDE;  // [1024]
    float* gate_s = h_s + HD;                  // [32]

    const int w = tid >> 5, lane = tid & 31;
    const int base = cta * 8;

    for (int i = tid; i < STEPS * 32; i += 256) {
        const int r = i >> 9, s = i & 511;
        const int net = s >> 8, sl = s & 255;
        const int q = r >> 3, u = r & 7;
        gsl[s * GSL_STRIDE + r] =
            g_G[(size_t)net * G4 * SLEN + (size_t)(q * HD + base + u) * SLEN + sl];
    }

    ulonglong2 wv[4][8];
    load_w(wv, encWhh, w, lane, base);

    float cstate = 0.f;
    if (tid < 8) {
        g_hbuf[0][base + tid] = 0.f;
        __syncwarp(0xff);
        if (tid == 0) red_rel(&g_cnt[0]);
    }
    __syncthreads();

    for (int t = 0; t < STEPS; t++) {
        if (t == SLEN) load_w(wv, decWhh, w, lane, base);

        if (tid == 0) { while (ld_acq(&g_cnt[t]) < NCTA_REC) {} }
        __syncthreads();
        ((float4*)h_s)[tid] = ((const float4*)g_hbuf[t & 1])[tid];
        __syncthreads();

        unsigned long long acc2[4] = {0ull, 0ull, 0ull, 0ull};
        #pragma unroll
        for (int c = 0; c < 8; c++) {
            const ulonglong2 hv = *(const ulonglong2*)(h_s + lane * 4 + c * 128);
            #pragma unroll
            for (int j = 0; j < 4; j++) {
                ffma2(acc2[j], wv[j][c].x, hv.x);
                ffma2(acc2[j], wv[j][c].y, hv.y);
            }
        }
        float accf[4];
        #pragma unroll
        for (int j = 0; j < 4; j++) {
            float lo, hi; unpack2(acc2[j], lo, hi);
            accf[j] = lo + hi;
        }
        #pragma unroll
        for (int off = 16; off; off >>= 1) {
            #pragma unroll
            for (int j = 0; j < 4; j++)
                accf[j] += __shfl_xor_sync(0xffffffffu, accf[j], off);
        }
        if (lane < 4) gate_s[w * 4 + lane] = accf[lane];
        __syncthreads();

        if (w == 0) {
            const int q = lane >> 3, u = lane & 7;
            const float val = gate_s[lane] + gsl[t * GSL_STRIDE + lane];
            const float act = (q == 2) ? tanh_hw(val) : sig_hw(val);
            const float iv = __shfl_sync(0xffffffffu, act, u);
            const float fv = __shfl_sync(0xffffffffu, act, u + 8);
            const float gv = __shfl_sync(0xffffffffu, act, u + 16);
            const float ov = __shfl_sync(0xffffffffu, act, u + 24);
            if (lane < 8) {
                cstate = fv * cstate + iv * gv;
                const float hh = ov * tanh_hw(cstate);
                g_hbuf[(t + 1) & 1][base + lane] = hh;
                if (t >= SLEN) g_Hbf[(size_t)(t - SLEN) * HD + base + lane] = __float2bfloat16(hh);
            }
            __syncwarp();
            if (lane == 0) red_rel(&g_cnt[t + 1]);
        }
    }
}

// ---------------- 5) logits = H @ linW^T + lin_b, staged+pipelined ----------------
__global__ void __launch_bounds__(256) logits_mma(const float* __restrict__ lin_b,
                                                  float* __restrict__ out) {
    extern __shared__ __nv_bfloat16 sm2[];
    const size_t bm = (size_t)blockIdx.x * 128;
    const int bn = blockIdx.y * 64;
    const int tid = threadIdx.x;
    const int w = tid >> 5, lane = tid & 31;
    const int group = lane >> 2, tig = lane & 3;

    float acc[8][4];
    tile_mainloop(g_linw_bf + bm * HD, g_Hbf + (size_t)bn * HD, sm2, tid, acc);

    const size_t m0 = bm + 16 * w + group;
    const float bias0 = lin_b[m0];
    const float bias8 = lin_b[m0 + 8];
    #pragma unroll
    for (int nf = 0; nf < 8; nf++) {
        const int n = bn + nf * 8 + 2 * tig;
        out[(size_t)n * VOUT + m0]           = acc[nf][0] + bias0;
        out[(size_t)(n + 1) * VOUT + m0]     = acc[nf][1] + bias0;
        out[(size_t)n * VOUT + m0 + 8]       = acc[nf][2] + bias8;
        out[(size_t)(n + 1) * VOUT + m0 + 8] = acc[nf][3] + bias8;
    }
}

// ---------------- 6) in-place row log_softmax (online, float4, 512 thr) ----------------
__global__ void __launch_bounds__(512) logsoftmax_kernel(float* __restrict__ out) {
    const int t = blockIdx.x;
    float* row = out + (size_t)t * VOUT;
    const int tid = threadIdx.x;
    __shared__ float smx[16], ssm[16];
    __shared__ float sbcast;

    float4* r4 = (float4*)row;
    float m = -3.4e38f, s = 0.f;
    for (int i = tid; i < VOUT / 4; i += 512) {
        const float4 v = r4[i];
        const float vm = fmaxf(fmaxf(v.x, v.y), fmaxf(v.z, v.w));
        const float nm = fmaxf(m, vm);
        s = s * __expf(m - nm) + __expf(v.x - nm) + __expf(v.y - nm)
                               + __expf(v.z - nm) + __expf(v.w - nm);
        m = nm;
    }
    #pragma unroll
    for (int o = 16; o; o >>= 1) {
        const float mo = __shfl_xor_sync(0xffffffffu, m, o);
        const float so = __shfl_xor_sync(0xffffffffu, s, o);
        const float nm = fmaxf(m, mo);
        s = s * __expf(m - nm) + so * __expf(mo - nm);
        m = nm;
    }
    if ((tid & 31) == 0) { smx[tid >> 5] = m; ssm[tid >> 5] = s; }
    __syncthreads();
    if (tid == 0) {
        float M = smx[0], S = ssm[0];
        for (int wq = 1; wq < 16; wq++) {
            const float nm = fmaxf(M, smx[wq]);
            S = S * __expf(M - nm) + ssm[wq] * __expf(smx[wq] - nm);
            M = nm;
        }
        sbcast = M + logf(S);
    }
    __syncthreads();
    const float lse = sbcast;
    for (int i = tid; i < VOUT / 4; i += 512) {
        float4 v = r4[i];
        v.x -= lse; v.y -= lse; v.z -= lse; v.w -= lse;
        r4[i] = v;
    }
}

// ---------------- launch ----------------
extern "C" void kernel_launch(void* const* d_in, const int* in_sizes, int n_in,
                              void* d_out, int out_size) {
    const int*   src     = (const int*)d_in[0];
    const int*   trg     = (const int*)d_in[1];
    const int*   start   = (const int*)d_in[2];
    const float* enc_emb = (const float*)d_in[3];
    const float* enc_Wih = (const float*)d_in[4];
    const float* enc_Whh = (const float*)d_in[5];
    const float* enc_bih = (const float*)d_in[6];
    const float* enc_bhh = (const float*)d_in[7];
    const float* dec_emb = (const float*)d_in[8];
    const float* dec_Wih = (const float*)d_in[9];
    const float* dec_Whh = (const float*)d_in[10];
    const float* dec_bih = (const float*)d_in[11];
    const float* dec_bhh = (const float*)d_in[12];
    const float* lin_W   = (const float*)d_in[13];
    const float* lin_b   = (const float*)d_in[14];
    float* out = (float*)d_out;

    prep_kernel<<<STEPS + 128, 256>>>(src, trg, start, enc_emb, dec_emb,
                                      enc_Wih, dec_Wih);

    cudaFuncSetAttribute(wx_mma, cudaFuncAttributeMaxDynamicSharedMemorySize, TILE_SMEM);
    dim3 gwx(G4 / 128, SLEN / 64, 2);
    wx_mma<<<gwx, 256, TILE_SMEM>>>(enc_bih, enc_bhh, dec_bih, dec_bhh);

    const int REC_SMEM = (STEPS * GSL_STRIDE + HD + 32) * 4;   // ~71.8 KB
    cudaFuncSetAttribute(rec_kernel, cudaFuncAttributeMaxDynamicSharedMemorySize, REC_SMEM);
    rec_kernel<<<NCTA_TOTAL, 256, REC_SMEM>>>(enc_Whh, dec_Whh, lin_W);

    cudaFuncSetAttribute(logits_mma, cudaFuncAttributeMaxDynamicSharedMemorySize, TILE_SMEM);
    dim3 gl(VTILES, TLEN / 64);
    logits_mma<<<gl, 256, TILE_SMEM>>>(lin_b, out);

    logsoftmax_kernel<<<TLEN, 512>>>(out);
}

// round 14
// speedup vs baseline: 1.1455x; 1.0024x over previous
#include <cuda_runtime.h>
#include <cuda_bf16.h>

#define HD    1024
#define SLEN  256
#define TLEN  256
#define VOUT  32000
#define G4    4096
#define NCTA_REC 128
#define NCTA_TOTAL 148
#define NSPARE (NCTA_TOTAL - NCTA_REC)
#define STEPS 512
#define GSL_STRIDE 33   // bank-conflict padding for gsl rows
#define LPAD 72         // smem row padding (bf16) for conflict-free ldmatrix
#define VTILES (VOUT / 128)
#define STAGE_ELEMS ((128 + 128) * LPAD)         // one pipeline stage (A+B), BN=128
#define TILE_SMEM (2 * STAGE_ELEMS * 2)          // 73728 B

// ---------------- device scratch ----------------
__device__ __nv_bfloat16 g_linw_bf[(size_t)VOUT * HD];   // 65.5 MB
__device__ __nv_bfloat16 g_wih_bf[2ul * G4 * HD];        // 16.8 MB
__device__ __nv_bfloat16 g_xbf[(size_t)STEPS * HD];      // 1 MB
__device__ float         g_G[2ul * G4 * SLEN];           // 8 MB, [net][gate_row][token]
__device__ __nv_bfloat16 g_Hbf[(size_t)TLEN * HD];       // 0.5 MB
__device__ float         g_hbuf[2][HD];
__device__ unsigned      g_cnt[STEPS + 1];

// ---------------- helpers ----------------
__device__ __forceinline__ void ffma2(unsigned long long &d,
                                      unsigned long long a, unsigned long long b) {
    asm("fma.rn.f32x2 %0, %1, %2, %0;" : "+l"(d) : "l"(a), "l"(b));
}
__device__ __forceinline__ void unpack2(unsigned long long v, float &lo, float &hi) {
    unsigned l, h;
    asm("mov.b64 {%0, %1}, %2;" : "=r"(l), "=r"(h) : "l"(v));
    lo = __uint_as_float(l); hi = __uint_as_float(h);
}
__device__ __forceinline__ unsigned ld_acq(const unsigned* p) {
    unsigned v;
    asm volatile("ld.acquire.gpu.global.u32 %0, [%1];" : "=r"(v) : "l"(p) : "memory");
    return v;
}
__device__ __forceinline__ void red_rel(unsigned* p) {
    asm volatile("red.release.gpu.global.add.u32 [%0], 1;" :: "l"(p) : "memory");
}
__device__ __forceinline__ float tanh_hw(float x) {
    float y;
    asm("tanh.approx.f32 %0, %1;" : "=f"(y) : "f"(x));
    return y;
}
__device__ __forceinline__ float sig_hw(float x) {
    return fmaf(tanh_hw(0.5f * x), 0.5f, 0.5f);
}
__device__ __forceinline__ void mma_bf16(float c[4],
                                         unsigned a0, unsigned a1, unsigned a2, unsigned a3,
                                         unsigned b0, unsigned b1) {
    asm volatile("mma.sync.aligned.m16n8k16.row.col.f32.bf16.bf16.f32 "
                 "{%0,%1,%2,%3}, {%4,%5,%6,%7}, {%8,%9}, {%0,%1,%2,%3};"
                 : "+f"(c[0]), "+f"(c[1]), "+f"(c[2]), "+f"(c[3])
                 : "r"(a0), "r"(a1), "r"(a2), "r"(a3), "r"(b0), "r"(b1));
}
__device__ __forceinline__ unsigned smem_u32(const void* p) {
    return (unsigned)__cvta_generic_to_shared(p);
}
__device__ __forceinline__ void ldsm_x4(unsigned &r0, unsigned &r1,
                                        unsigned &r2, unsigned &r3, unsigned addr) {
    asm volatile("ldmatrix.sync.aligned.m8n8.x4.shared.b16 {%0,%1,%2,%3}, [%4];"
                 : "=r"(r0), "=r"(r1), "=r"(r2), "=r"(r3) : "r"(addr));
}
__device__ __forceinline__ void cp16(void* smem, const void* gmem) {
    asm volatile("cp.async.cg.shared.global [%0], [%1], 16;"
                 :: "r"(smem_u32(smem)), "l"(gmem));
}
#define CP_COMMIT() asm volatile("cp.async.commit_group;" ::: "memory")
#define CP_WAIT1()  asm volatile("cp.async.wait_group 1;" ::: "memory")

// ---------------- double-buffered 128x128xK tile core ----------------
// A: 128 rows of HD bf16, B: 128 rows of HD bf16. Warp w owns A rows 16w..16w+15.
// acc[nf][q] covers 16 n-frags of 8 tokens.
__device__ __forceinline__ void tile_mainloop(const __nv_bfloat16* __restrict__ Abase,
                                              const __nv_bfloat16* __restrict__ Bbase,
                                              __nv_bfloat16* sm2, int tid,
                                              float acc[16][4]) {
    const int w = tid >> 5, lane = tid & 31;
    const int mi = lane >> 3, r8 = lane & 7;
    const int a_row = 16 * w + r8 + ((mi & 1) ? 8 : 0);
    const int a_col = (mi & 2) ? 8 : 0;

    #pragma unroll
    for (int nf = 0; nf < 16; nf++)
        #pragma unroll
        for (int q = 0; q < 4; q++) acc[nf][q] = 0.f;

    auto prefetch = [&](int k0, int st) {
        __nv_bfloat16* sA = sm2 + st * STAGE_ELEMS;
        __nv_bfloat16* sB = sA + 128 * LPAD;
        #pragma unroll
        for (int i = tid; i < 128 * 8; i += 256) {
            const int row = i >> 3, c = i & 7;
            cp16(&sA[row * LPAD + c * 8], &Abase[(size_t)row * HD + k0 + c * 8]);
        }
        #pragma unroll
        for (int i = tid; i < 128 * 8; i += 256) {
            const int row = i >> 3, c = i & 7;
            cp16(&sB[row * LPAD + c * 8], &Bbase[(size_t)row * HD + k0 + c * 8]);
        }
    };

    prefetch(0, 0);
    CP_COMMIT();

    #pragma unroll 1
    for (int it = 0; it < HD / 64; it++) {
        const int cur = it & 1;
        if (it + 1 < HD / 64) prefetch((it + 1) * 64, cur ^ 1);
        CP_COMMIT();
        CP_WAIT1();
        __syncthreads();

        __nv_bfloat16* sA = sm2 + cur * STAGE_ELEMS;
        __nv_bfloat16* sB = sA + 128 * LPAD;
        #pragma unroll
        for (int kk = 0; kk < 64; kk += 16) {
            unsigned a[4];
            ldsm_x4(a[0], a[1], a[2], a[3],
                    smem_u32(&sA[a_row * LPAD + kk + a_col]));
            #pragma unroll
            for (int p = 0; p < 8; p++) {
                unsigned b0, b1, b2, b3;
                const int b_row = (2 * p + (mi >> 1)) * 8 + r8;
                const int b_col = kk + ((mi & 1) ? 8 : 0);
                ldsm_x4(b0, b1, b2, b3, smem_u32(&sB[b_row * LPAD + b_col]));
                mma_bf16(acc[2 * p],     a[0], a[1], a[2], a[3], b0, b1);
                mma_bf16(acc[2 * p + 1], a[0], a[1], a[2], a[3], b2, b3);
            }
        }
        __syncthreads();
    }
}

// ---------------- 1) prep: embedding gather + Wih conversion + counter reset ----------------
__global__ void prep_kernel(const int* __restrict__ src, const int* __restrict__ trg,
                            const int* __restrict__ start,
                            const float* __restrict__ enc_emb,
                            const float* __restrict__ dec_emb,
                            const float* __restrict__ encWih,
                            const float* __restrict__ decWih) {
    const int b = blockIdx.x;           // 0..639
    const int tid = threadIdx.x;        // 256
    if (b < STEPS) {
        const int t = b;
        if (t == 0) {
            for (int i = tid; i < STEPS + 1; i += 256) g_cnt[i] = 0;
        }
        const float* emb; int tok;
        if (t < SLEN) { tok = src[t]; emb = enc_emb; }
        else {
            int tt = t - SLEN;
            tok = (tt == 0) ? start[0] : trg[tt - 1];
            emb = dec_emb;
        }
        const float4 v = ((const float4*)(emb + (size_t)tok * HD))[tid];
        __nv_bfloat162* d = (__nv_bfloat162*)(g_xbf + (size_t)t * HD);
        d[2 * tid]     = __floats2bfloat162_rn(v.x, v.y);
        d[2 * tid + 1] = __floats2bfloat162_rn(v.z, v.w);
    } else {
        const size_t NW4 = (size_t)G4 * HD / 4;
        size_t i = (size_t)(b - STEPS) * 256 + tid;
        const size_t stride = 128ul * 256;
        const float4* se = (const float4*)encWih;
        const float4* sd = (const float4*)decWih;
        __nv_bfloat162* de = (__nv_bfloat162*)g_wih_bf;
        __nv_bfloat162* dd = (__nv_bfloat162*)(g_wih_bf + (size_t)G4 * HD);
        for (size_t j = i; j < NW4; j += stride) {
            const float4 ve = se[j];
            de[2 * j]     = __floats2bfloat162_rn(ve.x, ve.y);
            de[2 * j + 1] = __floats2bfloat162_rn(ve.z, ve.w);
            const float4 vd = sd[j];
            dd[2 * j]     = __floats2bfloat162_rn(vd.x, vd.y);
            dd[2 * j + 1] = __floats2bfloat162_rn(vd.z, vd.w);
        }
    }
}

// ---------------- 3) G^T = Wih @ X^T + (bih+bhh), staged+pipelined, BN=128 ----------------
__global__ void __launch_bounds__(256) wx_mma(const float* __restrict__ eb_ih,
                                              const float* __restrict__ eb_hh,
                                              const float* __restrict__ db_ih,
                                              const float* __restrict__ db_hh) {
    extern __shared__ __nv_bfloat16 sm2[];
    const int net = blockIdx.z;
    const int bm = blockIdx.x * 128;
    const int bn = blockIdx.y * 128;
    const int tid = threadIdx.x;
    const int w = tid >> 5, lane = tid & 31;
    const int group = lane >> 2, tig = lane & 3;

    const __nv_bfloat16* Abase = g_wih_bf + (size_t)net * G4 * HD + (size_t)bm * HD;
    const __nv_bfloat16* Bbase = g_xbf + (size_t)net * SLEN * HD + (size_t)bn * HD;
    const float* bih = net ? db_ih : eb_ih;
    const float* bhh = net ? db_hh : eb_hh;
    float* Gout = g_G + (size_t)net * G4 * SLEN;

    float acc[16][4];
    tile_mainloop(Abase, Bbase, sm2, tid, acc);

    const int m0 = bm + 16 * w + group;
    const float bias0 = bih[m0] + bhh[m0];
    const float bias8 = bih[m0 + 8] + bhh[m0 + 8];
    #pragma unroll
    for (int nf = 0; nf < 16; nf++) {
        const int n = bn + nf * 8 + 2 * tig;
        float2 s0; s0.x = acc[nf][0] + bias0; s0.y = acc[nf][1] + bias0;
        float2 s8; s8.x = acc[nf][2] + bias8; s8.y = acc[nf][3] + bias8;
        *(float2*)&Gout[(size_t)m0 * SLEN + n]       = s0;
        *(float2*)&Gout[(size_t)(m0 + 8) * SLEN + n] = s8;
    }
}

// ---------------- 4) persistent LSTM recurrence + hidden linW conversion ----------------
__device__ __forceinline__ void load_w(ulonglong2 (&wv)[4][8], const float* __restrict__ W,
                                       int w, int lane, int base) {
    #pragma unroll
    for (int j = 0; j < 4; j++) {
        const int r = w * 4 + j, q = r >> 3, u = r & 7;
        const float* row = W + (size_t)(q * HD + base + u) * HD + lane * 4;
        #pragma unroll
        for (int c = 0; c < 8; c++)
            wv[j][c] = *(const ulonglong2*)(row + c * 128);
    }
}

__global__ void __launch_bounds__(256, 1) rec_kernel(const float* __restrict__ encWhh,
                                                     const float* __restrict__ decWhh,
                                                     const float* __restrict__ linW) {
    const int tid = threadIdx.x, cta = blockIdx.x;

    if (cta >= NCTA_REC) {
        // linW f32 -> bf16 on the 20 spare SMs (hidden under recurrence)
        const size_t NL4 = (size_t)VOUT * HD / 4;
        size_t i = (size_t)(cta - NCTA_REC) * 256 + tid;
        const size_t stride = (size_t)NSPARE * 256;
        const float4* src = (const float4*)linW;
        __nv_bfloat162* dst = (__nv_bfloat162*)g_linw_bf;
        for (size_t j = i; j < NL4; j += stride) {
            const float4 v = src[j];
            dst[2 * j]     = __floats2bfloat162_rn(v.x, v.y);
            dst[2 * j + 1] = __floats2bfloat162_rn(v.z, v.w);
        }
        return;
    }

    extern __shared__ float sm[];
    float* gsl    = sm;                        // [512][GSL_STRIDE] Wx+bias gates
    float* h_s    = gsl + STEPS * GSL_STRIDE;  // [1024]
    float* gate_s = h_s + HD;                  // [32]

    const int w = tid >> 5, lane = tid & 31;
    const int base = cta * 8;

    for (int i = tid; i < STEPS * 32; i += 256) {
        const int r = i >> 9, s = i & 511;
        const int net = s >> 8, sl = s & 255;
        const int q = r >> 3, u = r & 7;
        gsl[s * GSL_STRIDE + r] =
            g_G[(size_t)net * G4 * SLEN + (size_t)(q * HD + base + u) * SLEN + sl];
    }

    ulonglong2 wv[4][8];
    load_w(wv, encWhh, w, lane, base);

    float cstate = 0.f;
    if (tid < 8) {
        g_hbuf[0][base + tid] = 0.f;
        __syncwarp(0xff);
        if (tid == 0) red_rel(&g_cnt[0]);
    }
    __syncthreads();

    for (int t = 0; t < STEPS; t++) {
        if (t == SLEN) load_w(wv, decWhh, w, lane, base);

        if (tid == 0) { while (ld_acq(&g_cnt[t]) < NCTA_REC) {} }
        __syncthreads();
        ((float4*)h_s)[tid] = ((const float4*)g_hbuf[t & 1])[tid];
        __syncthreads();

        unsigned long long acc2[4] = {0ull, 0ull, 0ull, 0ull};
        #pragma unroll
        for (int c = 0; c < 8; c++) {
            const ulonglong2 hv = *(const ulonglong2*)(h_s + lane * 4 + c * 128);
            #pragma unroll
            for (int j = 0; j < 4; j++) {
                ffma2(acc2[j], wv[j][c].x, hv.x);
                ffma2(acc2[j], wv[j][c].y, hv.y);
            }
        }
        float accf[4];
        #pragma unroll
        for (int j = 0; j < 4; j++) {
            float lo, hi; unpack2(acc2[j], lo, hi);
            accf[j] = lo + hi;
        }
        #pragma unroll
        for (int off = 16; off; off >>= 1) {
            #pragma unroll
            for (int j = 0; j < 4; j++)
                accf[j] += __shfl_xor_sync(0xffffffffu, accf[j], off);
        }
        if (lane < 4) gate_s[w * 4 + lane] = accf[lane];
        __syncthreads();

        if (w == 0) {
            const int q = lane >> 3, u = lane & 7;
            const float val = gate_s[lane] + gsl[t * GSL_STRIDE + lane];
            const float act = (q == 2) ? tanh_hw(val) : sig_hw(val);
            const float iv = __shfl_sync(0xffffffffu, act, u);
            const float fv = __shfl_sync(0xffffffffu, act, u + 8);
            const float gv = __shfl_sync(0xffffffffu, act, u + 16);
            const float ov = __shfl_sync(0xffffffffu, act, u + 24);
            if (lane < 8) {
                cstate = fv * cstate + iv * gv;
                const float hh = ov * tanh_hw(cstate);
                g_hbuf[(t + 1) & 1][base + lane] = hh;
                if (t >= SLEN) g_Hbf[(size_t)(t - SLEN) * HD + base + lane] = __float2bfloat16(hh);
            }
            __syncwarp();
            if (lane == 0) red_rel(&g_cnt[t + 1]);
        }
    }
}

// ---------------- 5) logits = H @ linW^T + lin_b, staged+pipelined, BN=128 ----------------
__global__ void __launch_bounds__(256) logits_mma(const float* __restrict__ lin_b,
                                                  float* __restrict__ out) {
    extern __shared__ __nv_bfloat16 sm2[];
    const size_t bm = (size_t)blockIdx.x * 128;
    const int bn = blockIdx.y * 128;
    const int tid = threadIdx.x;
    const int w = tid >> 5, lane = tid & 31;
    const int group = lane >> 2, tig = lane & 3;

    float acc[16][4];
    tile_mainloop(g_linw_bf + bm * HD, g_Hbf + (size_t)bn * HD, sm2, tid, acc);

    const size_t m0 = bm + 16 * w + group;
    const float bias0 = lin_b[m0];
    const float bias8 = lin_b[m0 + 8];
    #pragma unroll
    for (int nf = 0; nf < 16; nf++) {
        const int n = bn + nf * 8 + 2 * tig;
        out[(size_t)n * VOUT + m0]           = acc[nf][0] + bias0;
        out[(size_t)(n + 1) * VOUT + m0]     = acc[nf][1] + bias0;
        out[(size_t)n * VOUT + m0 + 8]       = acc[nf][2] + bias8;
        out[(size_t)(n + 1) * VOUT + m0 + 8] = acc[nf][3] + bias8;
    }
}

// ---------------- 6) in-place row log_softmax (online, float4, 512 thr) ----------------
__global__ void __launch_bounds__(512) logsoftmax_kernel(float* __restrict__ out) {
    const int t = blockIdx.x;
    float* row = out + (size_t)t * VOUT;
    const int tid = threadIdx.x;
    __shared__ float smx[16], ssm[16];
    __shared__ float sbcast;

    float4* r4 = (float4*)row;
    float m = -3.4e38f, s = 0.f;
    for (int i = tid; i < VOUT / 4; i += 512) {
        const float4 v = r4[i];
        const float vm = fmaxf(fmaxf(v.x, v.y), fmaxf(v.z, v.w));
        const float nm = fmaxf(m, vm);
        s = s * __expf(m - nm) + __expf(v.x - nm) + __expf(v.y - nm)
                               + __expf(v.z - nm) + __expf(v.w - nm);
        m = nm;
    }
    #pragma unroll
    for (int o = 16; o; o >>= 1) {
        const float mo = __shfl_xor_sync(0xffffffffu, m, o);
        const float so = __shfl_xor_sync(0xffffffffu, s, o);
        const float nm = fmaxf(m, mo);
        s = s * __expf(m - nm) + so * __expf(mo - nm);
        m = nm;
    }
    if ((tid & 31) == 0) { smx[tid >> 5] = m; ssm[tid >> 5] = s; }
    __syncthreads();
    if (tid == 0) {
        float M = smx[0], S = ssm[0];
        for (int wq = 1; wq < 16; wq++) {
            const float nm = fmaxf(M, smx[wq]);
            S = S * __expf(M - nm) + ssm[wq] * __expf(smx[wq] - nm);
            M = nm;
        }
        sbcast = M + logf(S);
    }
    __syncthreads();
    const float lse = sbcast;
    for (int i = tid; i < VOUT / 4; i += 512) {
        float4 v = r4[i];
        v.x -= lse; v.y -= lse; v.z -= lse; v.w -= lse;
        r4[i] = v;
    }
}

// ---------------- launch ----------------
extern "C" void kernel_launch(void* const* d_in, const int* in_sizes, int n_in,
                              void* d_out, int out_size) {
    const int*   src     = (const int*)d_in[0];
    const int*   trg     = (const int*)d_in[1];
    const int*   start   = (const int*)d_in[2];
    const float* enc_emb = (const float*)d_in[3];
    const float* enc_Wih = (const float*)d_in[4];
    const float* enc_Whh = (const float*)d_in[5];
    const float* enc_bih = (const float*)d_in[6];
    const float* enc_bhh = (const float*)d_in[7];
    const float* dec_emb = (const float*)d_in[8];
    const float* dec_Wih = (const float*)d_in[9];
    const float* dec_Whh = (const float*)d_in[10];
    const float* dec_bih = (const float*)d_in[11];
    const float* dec_bhh = (const float*)d_in[12];
    const float* lin_W   = (const float*)d_in[13];
    const float* lin_b   = (const float*)d_in[14];
    float* out = (float*)d_out;

    prep_kernel<<<STEPS + 128, 256>>>(src, trg, start, enc_emb, dec_emb,
                                      enc_Wih, dec_Wih);

    cudaFuncSetAttribute(wx_mma, cudaFuncAttributeMaxDynamicSharedMemorySize, TILE_SMEM);
    dim3 gwx(G4 / 128, SLEN / 128, 2);
    wx_mma<<<gwx, 256, TILE_SMEM>>>(enc_bih, enc_bhh, dec_bih, dec_bhh);

    const int REC_SMEM = (STEPS * GSL_STRIDE + HD + 32) * 4;   // ~71.8 KB
    cudaFuncSetAttribute(rec_kernel, cudaFuncAttributeMaxDynamicSharedMemorySize, REC_SMEM);
    rec_kernel<<<NCTA_TOTAL, 256, REC_SMEM>>>(enc_Whh, dec_Whh, lin_W);

    cudaFuncSetAttribute(logits_mma, cudaFuncAttributeMaxDynamicSharedMemorySize, TILE_SMEM);
    dim3 gl(VTILES, TLEN / 128);
    logits_mma<<<gl, 256, TILE_SMEM>>>(lin_b, out);

    logsoftmax_kernel<<<TLEN, 512>>>(out);
}